// round 3
// baseline (speedup 1.0000x reference)
#include <cuda_runtime.h>
#include <cuda_bf16.h>

// ---------------------------------------------------------------------------
// Scratch buffers (allocation-free: __device__ globals)
//   Max intermediate: (N=2, C=64, 1024, 1024) = 134,217,728 floats = 512 MB
// ---------------------------------------------------------------------------
__device__ float g_bufA[2 * 64 * 1024 * 1024];
__device__ float g_bufB[2 * 64 * 1024 * 1024];
__device__ float g_h[2 * 1024 * 1024];  // pixel-shuffled image (N,1,1024,1024)

// ---------------------------------------------------------------------------
// conv3x3, stride 1, pad 1, bias-free, fused ReLU.
//   Tile: 32 (x) by 8 (y) output pixels, CO_TILE output channels per block.
//   Each thread: 4 output channels x 8 consecutive x-pixels (32 accumulators).
//   Input channels processed in chunks of CC (<=8) staged in smem.
//   smem input tile row stride 35 (odd) -> conflict-free LDS across the warp.
//   Weight reads are warp-uniform (one co-group per warp) -> LDS broadcast.
// ---------------------------------------------------------------------------
template <int CIN, int COUT>
__global__ void conv3x3_relu(const float* __restrict__ in,
                             const float* __restrict__ w,
                             float* __restrict__ out,
                             int H, int W) {
    constexpr int TW = 32, TH = 8;
    constexpr int CC = (CIN >= 8) ? 8 : CIN;              // cin chunk
    constexpr int CO_TILE = (COUT < 32) ? COUT : 32;      // 16, 25, or 32
    constexpr int CO_GROUPS = (CO_TILE + 3) / 4;
    constexpr int CO_PAD = CO_GROUPS * 4;                 // padded co per block
    constexpr int CO_TILES = (COUT + CO_TILE - 1) / CO_TILE;
    constexpr int SROW = TW + 3;                          // 35: odd stride

    __shared__ float s_in[CC][TH + 2][SROW];
    __shared__ float s_w[CO_PAD][CC][9];

    const int tid = threadIdx.x;
    const int nthreads = blockDim.x;          // 32 * CO_GROUPS

    const int n  = blockIdx.z / CO_TILES;
    const int ct = blockIdx.z % CO_TILES;
    const int gx0 = blockIdx.x * TW;
    const int gy0 = blockIdx.y * TH;

    const int pxg = tid & 31;                 // 0..31
    const int cog = tid >> 5;                 // 0..CO_GROUPS-1
    const int row = pxg >> 2;                 // 0..7  (output row in tile)
    const int x0  = (pxg & 3) * 8;            // 0,8,16,24
    const int co_base = ct * CO_TILE + cog * 4;

    float acc[4][8];
#pragma unroll
    for (int g = 0; g < 4; ++g)
#pragma unroll
        for (int p = 0; p < 8; ++p) acc[g][p] = 0.f;

    for (int c0 = 0; c0 < CIN; c0 += CC) {
        // ---- stage input chunk (halo'd tile, zero-padded at borders) ----
        constexpr int IN_ELEMS = CC * (TH + 2) * (TW + 2);
        for (int i = tid; i < IN_ELEMS; i += nthreads) {
            int c = i / ((TH + 2) * (TW + 2));
            int r = (i / (TW + 2)) % (TH + 2);
            int x = i % (TW + 2);
            int gy = gy0 + r - 1;
            int gx = gx0 + x - 1;
            float v = 0.f;
            if (gy >= 0 && gy < H && gx >= 0 && gx < W)
                v = in[((n * CIN + c0 + c) * H + gy) * W + gx];
            s_in[c][r][x] = v;
        }
        // ---- stage weights (zero-fill padded channels) ----
        constexpr int W_ELEMS = CO_PAD * CC * 9;
        for (int i = tid; i < W_ELEMS; i += nthreads) {
            int co  = i / (CC * 9);
            int rem = i % (CC * 9);
            int c = rem / 9, k = rem % 9;
            int cog_g = ct * CO_TILE + co;
            float v = 0.f;
            if (cog_g < COUT)
                v = w[(cog_g * CIN + c0 + c) * 9 + k];
            s_w[co][c][k] = v;
        }
        __syncthreads();

        // ---- accumulate ----
#pragma unroll
        for (int c = 0; c < CC; ++c) {
#pragma unroll
            for (int ky = 0; ky < 3; ++ky) {
                float iv[10];
#pragma unroll
                for (int i = 0; i < 10; ++i)
                    iv[i] = s_in[c][row + ky][x0 + i];
#pragma unroll
                for (int g = 0; g < 4; ++g) {
                    const float w0 = s_w[cog * 4 + g][c][ky * 3 + 0];
                    const float w1 = s_w[cog * 4 + g][c][ky * 3 + 1];
                    const float w2 = s_w[cog * 4 + g][c][ky * 3 + 2];
#pragma unroll
                    for (int p = 0; p < 8; ++p) {
                        acc[g][p] = fmaf(iv[p], w0, acc[g][p]);
                        acc[g][p] = fmaf(iv[p + 1], w1, acc[g][p]);
                        acc[g][p] = fmaf(iv[p + 2], w2, acc[g][p]);
                    }
                }
            }
        }
        __syncthreads();
    }

    // ---- fused ReLU + store ----
    const int gy = gy0 + row;
#pragma unroll
    for (int g = 0; g < 4; ++g) {
        const int co = co_base + g;
        if (co < COUT && gy < H) {
            float* op = &out[((n * COUT + co) * H + gy) * W + gx0 + x0];
#pragma unroll
            for (int p = 0; p < 8; ++p)
                if (gx0 + x0 + p < W) op[p] = fmaxf(acc[g][p], 0.f);
        }
    }
}

// ---------------------------------------------------------------------------
// PixelShuffle(4) + ReLU: (N,16,256,256) -> (N,1,1024,1024)
//   out[n, 4h+i, 4w+j] = relu(in[n, i*4+j, h, w])
// ---------------------------------------------------------------------------
__global__ void pixel_shuffle_relu(const float* __restrict__ in,
                                   float* __restrict__ out, int total) {
    int idx = blockIdx.x * blockDim.x + threadIdx.x;
    if (idx >= total) return;
    int x = idx & 1023;
    int y = (idx >> 10) & 1023;
    int n = idx >> 20;
    int c = (y & 3) * 4 + (x & 3);
    float v = in[((n * 16 + c) * 256 + (y >> 2)) * 256 + (x >> 2)];
    out[idx] = fmaxf(v, 0.f);
}

// ---------------------------------------------------------------------------
// Per-pixel 5x5 dynamic kernel conv + residual add.
//   out[n,y,x] = h[n,y,x] + sum_j hpad(y + j%5 - 2, x + j/5 - 2) * z[n,j,y,x]
//   (matches reference: channel j -> kw = j/5 (col offset), kh = j%5 (row)).
// ---------------------------------------------------------------------------
__global__ void pixel_conv_add(const float* __restrict__ h,
                               const float* __restrict__ z,
                               float* __restrict__ out) {
    const int HH = 1024, WW = 1024;
    __shared__ float sh[20][21];   // 16x16 tile + 2-halo, padded stride

    const int n   = blockIdx.z;
    const int gx0 = blockIdx.x * 16;
    const int gy0 = blockIdx.y * 16;
    const int tx = threadIdx.x, ty = threadIdx.y;
    const int tid = ty * 16 + tx;

    for (int i = tid; i < 400; i += 256) {
        int r = i / 20, c = i % 20;
        int gy = gy0 + r - 2, gx = gx0 + c - 2;
        float v = 0.f;
        if (gy >= 0 && gy < HH && gx >= 0 && gx < WW)
            v = h[(n * HH + gy) * WW + gx];
        sh[r][c] = v;
    }
    __syncthreads();

    const int y = gy0 + ty, x = gx0 + tx;
    float acc = sh[ty + 2][tx + 2];                 // residual h
    const float* zp = z + (n * 25 * HH + y) * WW + x;
#pragma unroll
    for (int j = 0; j < 25; ++j)
        acc = fmaf(sh[ty + (j % 5)][tx + (j / 5)], zp[j * HH * WW], acc);
    out[(n * HH + y) * WW + x] = acc;
}

// ---------------------------------------------------------------------------
// Launch plumbing
// ---------------------------------------------------------------------------
template <int CIN, int COUT>
static void launch_conv(const float* in, const float* w, float* out,
                        int N, int H, int W) {
    constexpr int CO_TILE = (COUT < 32) ? COUT : 32;
    constexpr int CO_GROUPS = (CO_TILE + 3) / 4;
    constexpr int CO_TILES = (COUT + CO_TILE - 1) / CO_TILE;
    dim3 grid(W / 32, H / 8, N * CO_TILES);
    conv3x3_relu<CIN, COUT><<<grid, 32 * CO_GROUPS>>>(in, w, out, H, W);
}

extern "C" void kernel_launch(void* const* d_in, const int* in_sizes, int n_in,
                              void* d_out, int out_size) {
    const float* x    = (const float*)d_in[0];
    const float* w_e1 = (const float*)d_in[1];
    const float* w_e2 = (const float*)d_in[2];
    const float* w_e3 = (const float*)d_in[3];
    const float* w_d1 = (const float*)d_in[4];
    const float* w_d2 = (const float*)d_in[5];
    const float* w_k1 = (const float*)d_in[6];
    const float* w_k2 = (const float*)d_in[7];
    const float* w_k3 = (const float*)d_in[8];
    const float* w_k4 = (const float*)d_in[9];
    float* out = (float*)d_out;

    const int N = in_sizes[0] / (256 * 256);   // N=2

    float *A, *B, *Hh;
    cudaGetSymbolAddress((void**)&A,  g_bufA);
    cudaGetSymbolAddress((void**)&B,  g_bufB);
    cudaGetSymbolAddress((void**)&Hh, g_h);

    // encoder / decoder @ 256x256
    launch_conv<1, 16>(x, w_e1, A, N, 256, 256);
    launch_conv<16, 32>(A, w_e2, B, N, 256, 256);
    launch_conv<32, 64>(B, w_e3, A, N, 256, 256);
    launch_conv<64, 32>(A, w_d1, B, N, 256, 256);
    launch_conv<32, 16>(B, w_d2, A, N, 256, 256);

    // pixel shuffle + relu -> (N,1,1024,1024)
    {
        int total = N * 1024 * 1024;
        pixel_shuffle_relu<<<(total + 255) / 256, 256>>>(A, Hh, total);
    }

    // kernel-prediction branch @ 1024x1024
    launch_conv<1, 32>(Hh, w_k1, A, N, 1024, 1024);
    launch_conv<32, 64>(A, w_k2, B, N, 1024, 1024);
    launch_conv<64, 32>(B, w_k3, A, N, 1024, 1024);
    launch_conv<32, 25>(A, w_k4, B, N, 1024, 1024);

    // per-pixel kernel application + residual
    {
        dim3 grid(1024 / 16, 1024 / 16, N);
        dim3 blk(16, 16);
        pixel_conv_add<<<grid, blk>>>(Hh, B, out);
    }
}

// round 7
// speedup vs baseline: 1.3412x; 1.3412x over previous
#include <cuda_runtime.h>
#include <cuda_bf16.h>
#include <cstdint>

// ---------------------------------------------------------------------------
// Scratch buffers (allocation-free: __device__ globals)
// ---------------------------------------------------------------------------
__device__ float g_bufA[2 * 64 * 1024 * 1024];
__device__ float g_bufB[2 * 64 * 1024 * 1024];
__device__ float g_h[2 * 1024 * 1024];  // pixel-shuffled image (N,1,1024,1024)

// ---------------------------------------------------------------------------
// Packed f32x2 helpers (sm_103a FFMA2 — 2 fp32 MACs per issue slot)
// ---------------------------------------------------------------------------
__device__ __forceinline__ void ffma2(uint64_t& d, uint64_t a, uint64_t b) {
    asm("fma.rn.f32x2 %0, %1, %2, %0;" : "+l"(d) : "l"(a), "l"(b));
}
__device__ __forceinline__ uint64_t dup2(float v) {
    uint32_t u = __float_as_uint(v);
    return (uint64_t)u | ((uint64_t)u << 32);
}
__device__ __forceinline__ uint64_t pack2(float lo, float hi) {
    return (uint64_t)__float_as_uint(lo) | ((uint64_t)__float_as_uint(hi) << 32);
}
__device__ __forceinline__ float lo_f(uint64_t v) { return __uint_as_float((uint32_t)v); }
__device__ __forceinline__ float hi_f(uint64_t v) { return __uint_as_float((uint32_t)(v >> 32)); }

// Threads per block for a given COUT — single source of truth, used by BOTH
// __launch_bounds__ and the launcher (R3 bug: these disagreed for COUT=25).
#define CONV_NT(COUT) \
    (((((((COUT) < 32) ? (COUT) : 32) + 7) & ~7) / 8) * 32)

// ---------------------------------------------------------------------------
// conv3x3 + ReLU, FFMA2 version.
//   Pixel tile 32x8. Thread: 8 consecutive x-pixels x 8 output channels
//   (4 packed co-pairs) = 32 f32x2 accumulators.
//   Input tile staged DUPLICATED ((v,v) per uint64) -> LDS.128 yields two
//   broadcast pairs; stride 34 (17 in 16B units, ==1 mod 8) is phase-minimal.
//   Weights staged packed (w[co], w[co+1]) -> warp-uniform LDS.64 broadcast.
// ---------------------------------------------------------------------------
template <int CIN, int COUT>
__global__ void __launch_bounds__(CONV_NT(COUT), 512 / CONV_NT(COUT))
conv3x3_relu2(const float* __restrict__ in,
              const float* __restrict__ w,
              float* __restrict__ out,
              int H, int W) {
    constexpr int CC = (CIN >= 8) ? 8 : CIN;              // cin chunk
    constexpr int CO_TILE = (COUT < 32) ? COUT : 32;      // co per block
    constexpr int CO_PAD = (CO_TILE + 7) & ~7;            // multiple of 8
    constexpr int CO_GROUPS = CO_PAD / 8;                 // 8 co per thread-group
    constexpr int CO_TILES = (COUT + CO_TILE - 1) / CO_TILE;
    constexpr int NT = CO_GROUPS * 32;                    // threads per block
    static_assert(NT == CONV_NT(COUT), "launch_bounds mismatch");
    constexpr int S2 = 34;                                // uint64 elems per row

    __shared__ __align__(16) uint64_t s_in2[CC][10][S2];        // duplicated input
    __shared__ __align__(16) uint64_t s_w2[CO_PAD / 2][CC][9];  // packed co-pairs

    const int tid = threadIdx.x;
    const int n  = blockIdx.z / CO_TILES;
    const int ct = blockIdx.z % CO_TILES;
    const int gx0 = blockIdx.x * 32;
    const int gy0 = blockIdx.y * 8;

    const int cog = tid >> 5;          // 0..CO_GROUPS-1
    const int pix = tid & 31;
    const int row = pix >> 2;          // 0..7
    const int x0  = (pix & 3) * 8;     // 0,8,16,24

    uint64_t acc[4][8];
#pragma unroll
    for (int g = 0; g < 4; ++g)
#pragma unroll
        for (int p = 0; p < 8; ++p) acc[g][p] = 0ull;

    for (int c0 = 0; c0 < CIN; c0 += CC) {
        // ---- stage input (duplicated), zero-padded halo ----
        constexpr int IN_ELEMS = CC * 10 * S2;
        for (int i = tid; i < IN_ELEMS; i += NT) {
            int c   = i / (10 * S2);
            int rem = i % (10 * S2);
            int r = rem / S2, sx = rem % S2;
            int gy = gy0 + r - 1, gx = gx0 + sx - 1;
            float v = 0.f;
            if ((unsigned)gy < (unsigned)H && (unsigned)gx < (unsigned)W)
                v = in[((n * CIN + c0 + c) * H + gy) * W + gx];
            (&s_in2[0][0][0])[i] = dup2(v);
        }
        // ---- stage weights as (co, co+1) pairs ----
        constexpr int W_ELEMS = (CO_PAD / 2) * CC * 9;
        for (int i = tid; i < W_ELEMS; i += NT) {
            int cp  = i / (CC * 9);
            int rem = i % (CC * 9);
            int c = rem / 9, k = rem % 9;
            int co0 = ct * CO_TILE + cp * 2;
            float a = (co0 < COUT)     ? w[((co0)     * CIN + c0 + c) * 9 + k] : 0.f;
            float b = (co0 + 1 < COUT) ? w[((co0 + 1) * CIN + c0 + c) * 9 + k] : 0.f;
            (&s_w2[0][0][0])[i] = pack2(a, b);
        }
        __syncthreads();

        // ---- accumulate ----
#pragma unroll 2
        for (int c = 0; c < CC; ++c) {
#pragma unroll
            for (int ky = 0; ky < 3; ++ky) {
                uint64_t P[10];
                const uint64_t* rowp = &s_in2[c][row + ky][x0];
#pragma unroll
                for (int t = 0; t < 5; ++t) {
                    ulonglong2 q = *reinterpret_cast<const ulonglong2*>(rowp + 2 * t);
                    P[2 * t]     = q.x;
                    P[2 * t + 1] = q.y;
                }
#pragma unroll
                for (int g = 0; g < 4; ++g) {
                    const uint64_t w0 = s_w2[cog * 4 + g][c][ky * 3 + 0];
                    const uint64_t w1 = s_w2[cog * 4 + g][c][ky * 3 + 1];
                    const uint64_t w2 = s_w2[cog * 4 + g][c][ky * 3 + 2];
#pragma unroll
                    for (int p = 0; p < 8; ++p) {
                        ffma2(acc[g][p], P[p],     w0);
                        ffma2(acc[g][p], P[p + 1], w1);
                        ffma2(acc[g][p], P[p + 2], w2);
                    }
                }
            }
        }
        __syncthreads();
    }

    // ---- fused ReLU + vectorized store ----
    const int gy = gy0 + row;
#pragma unroll
    for (int g = 0; g < 4; ++g) {
        const int co0 = ct * CO_TILE + cog * 8 + 2 * g;
        if (co0 < COUT) {
            float4 a, b;
            a.x = fmaxf(lo_f(acc[g][0]), 0.f); a.y = fmaxf(lo_f(acc[g][1]), 0.f);
            a.z = fmaxf(lo_f(acc[g][2]), 0.f); a.w = fmaxf(lo_f(acc[g][3]), 0.f);
            b.x = fmaxf(lo_f(acc[g][4]), 0.f); b.y = fmaxf(lo_f(acc[g][5]), 0.f);
            b.z = fmaxf(lo_f(acc[g][6]), 0.f); b.w = fmaxf(lo_f(acc[g][7]), 0.f);
            float4* op = (float4*)&out[((n * COUT + co0) * H + gy) * W + gx0 + x0];
            op[0] = a; op[1] = b;
        }
        if (co0 + 1 < COUT) {
            float4 a, b;
            a.x = fmaxf(hi_f(acc[g][0]), 0.f); a.y = fmaxf(hi_f(acc[g][1]), 0.f);
            a.z = fmaxf(hi_f(acc[g][2]), 0.f); a.w = fmaxf(hi_f(acc[g][3]), 0.f);
            b.x = fmaxf(hi_f(acc[g][4]), 0.f); b.y = fmaxf(hi_f(acc[g][5]), 0.f);
            b.z = fmaxf(hi_f(acc[g][6]), 0.f); b.w = fmaxf(hi_f(acc[g][7]), 0.f);
            float4* op = (float4*)&out[((n * COUT + co0 + 1) * H + gy) * W + gx0 + x0];
            op[0] = a; op[1] = b;
        }
    }
}

// ---------------------------------------------------------------------------
// PixelShuffle(4) + ReLU: (N,16,256,256) -> (N,1,1024,1024)
// ---------------------------------------------------------------------------
__global__ void pixel_shuffle_relu(const float* __restrict__ in,
                                   float* __restrict__ out, int total) {
    int idx = blockIdx.x * blockDim.x + threadIdx.x;
    if (idx >= total) return;
    int x = idx & 1023;
    int y = (idx >> 10) & 1023;
    int n = idx >> 20;
    int c = (y & 3) * 4 + (x & 3);
    float v = in[((n * 16 + c) * 256 + (y >> 2)) * 256 + (x >> 2)];
    out[idx] = fmaxf(v, 0.f);
}

// ---------------------------------------------------------------------------
// Per-pixel 5x5 dynamic kernel conv + residual add.
//   out[n,y,x] = h[n,y,x] + sum_j hpad(y + j%5 - 2, x + j/5 - 2) * z[n,j,y,x]
// ---------------------------------------------------------------------------
__global__ void pixel_conv_add(const float* __restrict__ h,
                               const float* __restrict__ z,
                               float* __restrict__ out) {
    const int HH = 1024, WW = 1024;
    __shared__ float sh[20][21];

    const int n   = blockIdx.z;
    const int gx0 = blockIdx.x * 16;
    const int gy0 = blockIdx.y * 16;
    const int tx = threadIdx.x, ty = threadIdx.y;
    const int tid = ty * 16 + tx;

    for (int i = tid; i < 400; i += 256) {
        int r = i / 20, c = i % 20;
        int gy = gy0 + r - 2, gx = gx0 + c - 2;
        float v = 0.f;
        if (gy >= 0 && gy < HH && gx >= 0 && gx < WW)
            v = h[(n * HH + gy) * WW + gx];
        sh[r][c] = v;
    }
    __syncthreads();

    const int y = gy0 + ty, x = gx0 + tx;
    float acc = sh[ty + 2][tx + 2];
    const float* zp = z + (n * 25 * HH + y) * WW + x;
#pragma unroll
    for (int j = 0; j < 25; ++j)
        acc = fmaf(sh[ty + (j % 5)][tx + (j / 5)], zp[j * HH * WW], acc);
    out[(n * HH + y) * WW + x] = acc;
}

// ---------------------------------------------------------------------------
// Launch plumbing
// ---------------------------------------------------------------------------
template <int CIN, int COUT>
static void launch_conv(const float* in, const float* w, float* out,
                        int N, int H, int W) {
    constexpr int CO_TILE = (COUT < 32) ? COUT : 32;
    constexpr int CO_TILES = (COUT + CO_TILE - 1) / CO_TILE;
    dim3 grid(W / 32, H / 8, N * CO_TILES);
    conv3x3_relu2<CIN, COUT><<<grid, CONV_NT(COUT)>>>(in, w, out, H, W);
}

extern "C" void kernel_launch(void* const* d_in, const int* in_sizes, int n_in,
                              void* d_out, int out_size) {
    const float* x    = (const float*)d_in[0];
    const float* w_e1 = (const float*)d_in[1];
    const float* w_e2 = (const float*)d_in[2];
    const float* w_e3 = (const float*)d_in[3];
    const float* w_d1 = (const float*)d_in[4];
    const float* w_d2 = (const float*)d_in[5];
    const float* w_k1 = (const float*)d_in[6];
    const float* w_k2 = (const float*)d_in[7];
    const float* w_k3 = (const float*)d_in[8];
    const float* w_k4 = (const float*)d_in[9];
    float* out = (float*)d_out;

    const int N = in_sizes[0] / (256 * 256);   // N=2

    float *A, *B, *Hh;
    cudaGetSymbolAddress((void**)&A,  g_bufA);
    cudaGetSymbolAddress((void**)&B,  g_bufB);
    cudaGetSymbolAddress((void**)&Hh, g_h);

    // encoder / decoder @ 256x256
    launch_conv<1, 16>(x, w_e1, A, N, 256, 256);
    launch_conv<16, 32>(A, w_e2, B, N, 256, 256);
    launch_conv<32, 64>(B, w_e3, A, N, 256, 256);
    launch_conv<64, 32>(A, w_d1, B, N, 256, 256);
    launch_conv<32, 16>(B, w_d2, A, N, 256, 256);

    // pixel shuffle + relu -> (N,1,1024,1024)
    {
        int total = N * 1024 * 1024;
        pixel_shuffle_relu<<<(total + 255) / 256, 256>>>(A, Hh, total);
    }

    // kernel-prediction branch @ 1024x1024
    launch_conv<1, 32>(Hh, w_k1, A, N, 1024, 1024);
    launch_conv<32, 64>(A, w_k2, B, N, 1024, 1024);
    launch_conv<64, 32>(B, w_k3, A, N, 1024, 1024);
    launch_conv<32, 25>(A, w_k4, B, N, 1024, 1024);

    // per-pixel kernel application + residual
    {
        dim3 grid(1024 / 16, 1024 / 16, N);
        dim3 blk(16, 16);
        pixel_conv_add<<<grid, blk>>>(Hh, B, out);
    }
}

// round 10
// speedup vs baseline: 1.4728x; 1.0981x over previous
#include <cuda_runtime.h>
#include <cuda_bf16.h>
#include <cstdint>

// ---------------------------------------------------------------------------
// Scratch buffers (allocation-free: __device__ globals)
// ---------------------------------------------------------------------------
__device__ float g_bufA[2 * 64 * 1024 * 1024];
__device__ float g_bufB[2 * 64 * 1024 * 1024];
__device__ float g_h[2 * 1024 * 1024];  // pixel-shuffled image (N,1,1024,1024)

// ---------------------------------------------------------------------------
// Packed f32x2 helpers (sm_103a FFMA2 — 2 fp32 MACs per issue slot)
// ---------------------------------------------------------------------------
__device__ __forceinline__ void ffma2(uint64_t& d, uint64_t a, uint64_t b) {
    asm("fma.rn.f32x2 %0, %1, %2, %0;" : "+l"(d) : "l"(a), "l"(b));
}
__device__ __forceinline__ uint64_t dup2(float v) {
    uint32_t u = __float_as_uint(v);
    return (uint64_t)u | ((uint64_t)u << 32);
}
__device__ __forceinline__ uint64_t pack2(float lo, float hi) {
    return (uint64_t)__float_as_uint(lo) | ((uint64_t)__float_as_uint(hi) << 32);
}
__device__ __forceinline__ float lo_f(uint64_t v) { return __uint_as_float((uint32_t)v); }
__device__ __forceinline__ float hi_f(uint64_t v) { return __uint_as_float((uint32_t)(v >> 32)); }

// Threads per block: one co-tile now covers ALL of COUT (16->64t, 25/32->128t, 64->256t)
#define CONV_NT2(COUT) (((((COUT) >= 64) ? 64 : (((COUT) + 7) & ~7)) / 8) * 32)

// ---------------------------------------------------------------------------
// conv3x3 + ReLU, FFMA2, software-pipelined staging (double-buffered smem).
//   Pixel tile 32x8. Thread: 8 x-pixels x 8 output channels (4 f32x2 pairs).
//   Per chunk (CC=4 input channels): prefetch next chunk's globals to regs,
//   compute current buffer, STS to alternate buffer, ONE sync per chunk.
// ---------------------------------------------------------------------------
template <int CIN, int COUT>
__global__ void __launch_bounds__(CONV_NT2(COUT), 512 / CONV_NT2(COUT))
conv3x3_pipe(const float* __restrict__ in,
             const float* __restrict__ w,
             float* __restrict__ out,
             int H, int W) {
    constexpr int CO_PAD    = (COUT >= 64) ? 64 : ((COUT + 7) & ~7);  // 16/32/32/64
    constexpr int CO_GROUPS = CO_PAD / 8;
    constexpr int NT        = CO_GROUPS * 32;
    static_assert(NT == CONV_NT2(COUT), "launch bounds mismatch");
    constexpr int CC     = (CIN >= 4) ? 4 : CIN;
    constexpr int NCHUNK = CIN / CC;
    constexpr int S2     = 34;                       // u64 elems per smem row
    constexpr int IN_ELEMS = CC * 10 * S2;
    constexpr int W_ELEMS  = (CO_PAD / 2) * CC * 9;
    constexpr int PF_IN = (IN_ELEMS + NT - 1) / NT;
    constexpr int PF_W  = (W_ELEMS + NT - 1) / NT;
    constexpr bool PIPE = (NT >= 128) && (NCHUNK > 1);
    constexpr int NBUF  = PIPE ? 2 : 1;

    __shared__ __align__(16) uint64_t s_in2[NBUF][CC][10][S2];
    __shared__ __align__(16) uint64_t s_w2[NBUF][CO_PAD / 2][CC][9];

    const int tid = threadIdx.x;
    const int n   = blockIdx.z;
    const int gx0 = blockIdx.x * 32;
    const int gy0 = blockIdx.y * 8;

    const int cog = tid >> 5;          // co-group 0..CO_GROUPS-1
    const int pix = tid & 31;
    const int row = pix >> 2;          // 0..7
    const int x0  = (pix & 3) * 8;     // 0,8,16,24

    uint64_t acc[4][8];
#pragma unroll
    for (int g = 0; g < 4; ++g)
#pragma unroll
        for (int p = 0; p < 8; ++p) acc[g][p] = 0ull;

    float vi[PF_IN];
    float vw[2 * PF_W];

    // ---- staging helpers ----
    auto ldg_in = [&](int c0) {
#pragma unroll
        for (int t = 0; t < PF_IN; ++t) {
            int i = tid + t * NT;
            float v = 0.f;
            if (i < IN_ELEMS) {
                int c = i / (10 * S2);
                int rem = i % (10 * S2);
                int r = rem / S2, sx = rem % S2;
                int gy = gy0 + r - 1, gx = gx0 + sx - 1;
                if ((unsigned)gy < (unsigned)H && (unsigned)gx < (unsigned)W)
                    v = in[((n * CIN + c0 + c) * H + gy) * W + gx];
            }
            vi[t] = v;
        }
    };
    auto ldg_w = [&](int c0) {
#pragma unroll
        for (int t = 0; t < PF_W; ++t) {
            int i = tid + t * NT;
            float a = 0.f, b = 0.f;
            if (i < W_ELEMS) {
                int cp = i / (CC * 9);
                int rem = i % (CC * 9);
                int c = rem / 9, k = rem % 9;
                int co0 = cp * 2;
                if (co0 < COUT)     a = w[((co0)     * CIN + c0 + c) * 9 + k];
                if (co0 + 1 < COUT) b = w[((co0 + 1) * CIN + c0 + c) * 9 + k];
            }
            vw[2 * t] = a; vw[2 * t + 1] = b;
        }
    };
    auto sts_chunk = [&](int buf) {
#pragma unroll
        for (int t = 0; t < PF_IN; ++t) {
            int i = tid + t * NT;
            if (i < IN_ELEMS) (&s_in2[buf][0][0][0])[i] = dup2(vi[t]);
        }
#pragma unroll
        for (int t = 0; t < PF_W; ++t) {
            int i = tid + t * NT;
            if (i < W_ELEMS) (&s_w2[buf][0][0][0])[i] = pack2(vw[2 * t], vw[2 * t + 1]);
        }
    };
    auto compute = [&](int buf) {
#pragma unroll 2
        for (int c = 0; c < CC; ++c) {
#pragma unroll
            for (int ky = 0; ky < 3; ++ky) {
                uint64_t P[10];
                const uint64_t* rowp = &s_in2[buf][c][row + ky][x0];
#pragma unroll
                for (int t = 0; t < 5; ++t) {
                    ulonglong2 q = *reinterpret_cast<const ulonglong2*>(rowp + 2 * t);
                    P[2 * t]     = q.x;
                    P[2 * t + 1] = q.y;
                }
#pragma unroll
                for (int g = 0; g < 4; ++g) {
                    const uint64_t w0 = s_w2[buf][cog * 4 + g][c][ky * 3 + 0];
                    const uint64_t w1 = s_w2[buf][cog * 4 + g][c][ky * 3 + 1];
                    const uint64_t w2 = s_w2[buf][cog * 4 + g][c][ky * 3 + 2];
#pragma unroll
                    for (int p = 0; p < 8; ++p) {
                        ffma2(acc[g][p], P[p],     w0);
                        ffma2(acc[g][p], P[p + 1], w1);
                        ffma2(acc[g][p], P[p + 2], w2);
                    }
                }
            }
        }
    };

    if (PIPE) {
        // prologue: stage chunk 0 into buffer 0
        ldg_in(0); ldg_w(0); sts_chunk(0);
        __syncthreads();
        for (int ch = 0; ch < NCHUNK; ++ch) {
            const int cur = ch & 1;
            if (ch + 1 < NCHUNK) ldg_in((ch + 1) * CC);   // in flight during compute
            compute(cur);
            if (ch + 1 < NCHUNK) {
                ldg_w((ch + 1) * CC);                      // small, L2-hot
                sts_chunk(cur ^ 1);
            }
            __syncthreads();                               // one sync per chunk
        }
    } else {
        for (int ch = 0; ch < NCHUNK; ++ch) {
            ldg_in(ch * CC); ldg_w(ch * CC);
            if (ch) __syncthreads();                       // all done reading buf
            sts_chunk(0);
            __syncthreads();
            compute(0);
        }
    }

    // ---- fused ReLU + vectorized store ----
    const int gy = gy0 + row;
#pragma unroll
    for (int g = 0; g < 4; ++g) {
        const int co0 = cog * 8 + 2 * g;
        if (co0 < COUT) {
            float4 a, b;
            a.x = fmaxf(lo_f(acc[g][0]), 0.f); a.y = fmaxf(lo_f(acc[g][1]), 0.f);
            a.z = fmaxf(lo_f(acc[g][2]), 0.f); a.w = fmaxf(lo_f(acc[g][3]), 0.f);
            b.x = fmaxf(lo_f(acc[g][4]), 0.f); b.y = fmaxf(lo_f(acc[g][5]), 0.f);
            b.z = fmaxf(lo_f(acc[g][6]), 0.f); b.w = fmaxf(lo_f(acc[g][7]), 0.f);
            float4* op = (float4*)&out[((n * COUT + co0) * H + gy) * W + gx0 + x0];
            op[0] = a; op[1] = b;
        }
        if (co0 + 1 < COUT) {
            float4 a, b;
            a.x = fmaxf(hi_f(acc[g][0]), 0.f); a.y = fmaxf(hi_f(acc[g][1]), 0.f);
            a.z = fmaxf(hi_f(acc[g][2]), 0.f); a.w = fmaxf(hi_f(acc[g][3]), 0.f);
            b.x = fmaxf(hi_f(acc[g][4]), 0.f); b.y = fmaxf(hi_f(acc[g][5]), 0.f);
            b.z = fmaxf(hi_f(acc[g][6]), 0.f); b.w = fmaxf(hi_f(acc[g][7]), 0.f);
            float4* op = (float4*)&out[((n * COUT + co0 + 1) * H + gy) * W + gx0 + x0];
            op[0] = a; op[1] = b;
        }
    }
}

// ---------------------------------------------------------------------------
// PixelShuffle(4) + ReLU: (N,16,256,256) -> (N,1,1024,1024)
// ---------------------------------------------------------------------------
__global__ void pixel_shuffle_relu(const float* __restrict__ in,
                                   float* __restrict__ out, int total) {
    int idx = blockIdx.x * blockDim.x + threadIdx.x;
    if (idx >= total) return;
    int x = idx & 1023;
    int y = (idx >> 10) & 1023;
    int n = idx >> 20;
    int c = (y & 3) * 4 + (x & 3);
    float v = in[((n * 16 + c) * 256 + (y >> 2)) * 256 + (x >> 2)];
    out[idx] = fmaxf(v, 0.f);
}

// ---------------------------------------------------------------------------
// Per-pixel 5x5 dynamic kernel conv + residual add.
//   out[n,y,x] = h[n,y,x] + sum_j hpad(y + j%5 - 2, x + j/5 - 2) * z[n,j,y,x]
// ---------------------------------------------------------------------------
__global__ void pixel_conv_add(const float* __restrict__ h,
                               const float* __restrict__ z,
                               float* __restrict__ out) {
    const int HH = 1024, WW = 1024;
    __shared__ float sh[20][21];

    const int n   = blockIdx.z;
    const int gx0 = blockIdx.x * 16;
    const int gy0 = blockIdx.y * 16;
    const int tx = threadIdx.x, ty = threadIdx.y;
    const int tid = ty * 16 + tx;

    for (int i = tid; i < 400; i += 256) {
        int r = i / 20, c = i % 20;
        int gy = gy0 + r - 2, gx = gx0 + c - 2;
        float v = 0.f;
        if (gy >= 0 && gy < HH && gx >= 0 && gx < WW)
            v = h[(n * HH + gy) * WW + gx];
        sh[r][c] = v;
    }
    __syncthreads();

    const int y = gy0 + ty, x = gx0 + tx;
    float acc = sh[ty + 2][tx + 2];
    const float* zp = z + (n * 25 * HH + y) * WW + x;
#pragma unroll
    for (int j = 0; j < 25; ++j)
        acc = fmaf(sh[ty + (j % 5)][tx + (j / 5)], zp[j * HH * WW], acc);
    out[(n * HH + y) * WW + x] = acc;
}

// ---------------------------------------------------------------------------
// Launch plumbing — one co-tile covers all COUT; grid z = batch only.
// ---------------------------------------------------------------------------
template <int CIN, int COUT>
static void launch_conv(const float* in, const float* w, float* out,
                        int N, int H, int W) {
    dim3 grid(W / 32, H / 8, N);
    conv3x3_pipe<CIN, COUT><<<grid, CONV_NT2(COUT)>>>(in, w, out, H, W);
}

extern "C" void kernel_launch(void* const* d_in, const int* in_sizes, int n_in,
                              void* d_out, int out_size) {
    const float* x    = (const float*)d_in[0];
    const float* w_e1 = (const float*)d_in[1];
    const float* w_e2 = (const float*)d_in[2];
    const float* w_e3 = (const float*)d_in[3];
    const float* w_d1 = (const float*)d_in[4];
    const float* w_d2 = (const float*)d_in[5];
    const float* w_k1 = (const float*)d_in[6];
    const float* w_k2 = (const float*)d_in[7];
    const float* w_k3 = (const float*)d_in[8];
    const float* w_k4 = (const float*)d_in[9];
    float* out = (float*)d_out;

    const int N = in_sizes[0] / (256 * 256);   // N=2

    float *A, *B, *Hh;
    cudaGetSymbolAddress((void**)&A,  g_bufA);
    cudaGetSymbolAddress((void**)&B,  g_bufB);
    cudaGetSymbolAddress((void**)&Hh, g_h);

    // encoder / decoder @ 256x256
    launch_conv<1, 16>(x, w_e1, A, N, 256, 256);
    launch_conv<16, 32>(A, w_e2, B, N, 256, 256);
    launch_conv<32, 64>(B, w_e3, A, N, 256, 256);
    launch_conv<64, 32>(A, w_d1, B, N, 256, 256);
    launch_conv<32, 16>(B, w_d2, A, N, 256, 256);

    // pixel shuffle + relu -> (N,1,1024,1024)
    {
        int total = N * 1024 * 1024;
        pixel_shuffle_relu<<<(total + 255) / 256, 256>>>(A, Hh, total);
    }

    // kernel-prediction branch @ 1024x1024
    launch_conv<1, 32>(Hh, w_k1, A, N, 1024, 1024);
    launch_conv<32, 64>(A, w_k2, B, N, 1024, 1024);
    launch_conv<64, 32>(B, w_k3, A, N, 1024, 1024);
    launch_conv<32, 25>(A, w_k4, B, N, 1024, 1024);

    // per-pixel kernel application + residual
    {
        dim3 grid(1024 / 16, 1024 / 16, N);
        dim3 blk(16, 16);
        pixel_conv_add<<<grid, blk>>>(Hh, B, out);
    }
}